// round 5
// baseline (speedup 1.0000x reference)
#include <cuda_runtime.h>
#include <cuda_bf16.h>
#include <cstdint>

// Problem constants
#define LSEQ 128
#define BATCH 64
#define EMB 512
#define HID 512          // per direction
#define G4 2048          // 4*HID
#define MROWS 8192       // LSEQ*BATCH
#define NCOLS 4096       // 2 directions * 4H
#define NBLK_REC 128     // recurrence CTAs (2 dirs * 64)

// ---------------------------------------------------------------------------
// Scratch (device globals; no allocations allowed)
// ---------------------------------------------------------------------------
__device__ float d_emb[(size_t)MROWS * EMB];          // 16 MB
__device__ float d_Xf [(size_t)MROWS * G4];           // 64 MB  (x@Wih_f^T + bias_f)
__device__ float d_Xb [(size_t)MROWS * G4];           // 64 MB
__device__ float d_h  [2 * 2 * BATCH * HID];          // [buf][dir][b][k]
__device__ volatile unsigned int d_bar_count;
__device__ volatile unsigned int d_bar_gen;

// ---------------------------------------------------------------------------
// 1) Embedding gather:  emb[t*B+b][e] = (data==-1) ? 0 : table[data][e]
// ---------------------------------------------------------------------------
__global__ void k_embed(const int* __restrict__ data,
                        const float* __restrict__ table) {
    int i = blockIdx.x * blockDim.x + threadIdx.x;      // float4 index
    if (i >= MROWS * (EMB / 4)) return;
    int m  = i >> 7;            // EMB/4 = 128 float4 per row
    int e4 = i & 127;
    int w  = data[m];
    float4 v = make_float4(0.f, 0.f, 0.f, 0.f);
    if (w >= 0) v = *(const float4*)(table + (size_t)w * EMB + e4 * 4);
    *(float4*)(d_emb + (size_t)m * EMB + e4 * 4) = v;
}

// ---------------------------------------------------------------------------
// 2) Input projection GEMM:  C[m][n] = emb[m][:] . W[n][:] + bias[n]
//    n in [0,2048) -> forward (Wih_f, bih_f+bhh_f) into d_Xf
//    n in [2048,4096) -> backward into d_Xb
//    BM=128, BN=128, BK=8, 256 threads, 8x8 micro-tile
// ---------------------------------------------------------------------------
__global__ void __launch_bounds__(256, 2)
k_gemm(const float* __restrict__ Wf, const float* __restrict__ Wb,
       const float* __restrict__ bihf, const float* __restrict__ bhhf,
       const float* __restrict__ bihb, const float* __restrict__ bhhb) {
    __shared__ float As[8][132];
    __shared__ float Bs[8][132];

    const int tid = threadIdx.x;
    const int n0 = blockIdx.x * 128;
    const int m0 = blockIdx.y * 128;
    const int tx = tid & 15, ty = tid >> 4;     // 16x16 threads
    const int lm = tid >> 1;                    // 0..127 : tile row for loads
    const int lk = (tid & 1) * 4;               // 0 or 4 : k offset for loads

    // B-source row pointer (tile is entirely fwd or entirely bwd: 128 | 2048)
    const int gn = n0 + lm;
    const float* wrow = (gn < G4) ? (Wf + (size_t)gn * EMB)
                                  : (Wb + (size_t)(gn - G4) * EMB);
    const float* arow = d_emb + (size_t)(m0 + lm) * EMB;

    float acc[8][8];
#pragma unroll
    for (int i = 0; i < 8; i++)
#pragma unroll
        for (int j = 0; j < 8; j++) acc[i][j] = 0.f;

    for (int k0 = 0; k0 < EMB; k0 += 8) {
        float4 av = *(const float4*)(arow + k0 + lk);
        float4 bv = *(const float4*)(wrow + k0 + lk);
        __syncthreads();
        As[lk + 0][lm] = av.x; As[lk + 1][lm] = av.y;
        As[lk + 2][lm] = av.z; As[lk + 3][lm] = av.w;
        Bs[lk + 0][lm] = bv.x; Bs[lk + 1][lm] = bv.y;
        Bs[lk + 2][lm] = bv.z; Bs[lk + 3][lm] = bv.w;
        __syncthreads();
#pragma unroll
        for (int kk = 0; kk < 8; kk++) {
            float a[8], b[8];
            *(float4*)(a    ) = *(const float4*)&As[kk][ty * 8    ];
            *(float4*)(a + 4) = *(const float4*)&As[kk][ty * 8 + 4];
            *(float4*)(b    ) = *(const float4*)&Bs[kk][tx * 8    ];
            *(float4*)(b + 4) = *(const float4*)&Bs[kk][tx * 8 + 4];
#pragma unroll
            for (int i = 0; i < 8; i++)
#pragma unroll
                for (int j = 0; j < 8; j++)
                    acc[i][j] += a[i] * b[j];
        }
    }

    // Epilogue: add bias, write to Xf/Xb
    const bool fwd = (n0 < G4);
    const int nb = fwd ? n0 : (n0 - G4);
    const float* bi = fwd ? bihf : bihb;
    const float* bh = fwd ? bhhf : bhhb;
    float* dstbase = fwd ? d_Xf : d_Xb;
#pragma unroll
    for (int i = 0; i < 8; i++) {
        int m = m0 + ty * 8 + i;
        float* drow = dstbase + (size_t)m * G4 + nb + tx * 8;
#pragma unroll
        for (int j = 0; j < 8; j++) {
            int n = nb + tx * 8 + j;
            drow[j] = acc[i][j] + bi[n] + bh[n];
        }
    }
}

// ---------------------------------------------------------------------------
// 3) Init: zero h buffer 0 (both dirs), reset barrier.
// ---------------------------------------------------------------------------
__global__ void k_init() {
    int i = blockIdx.x * blockDim.x + threadIdx.x;
    if (i < 2 * BATCH * HID) d_h[i] = 0.f;
    if (i == 0) { d_bar_count = 0u; d_bar_gen = 0u; }
}

// ---------------------------------------------------------------------------
// 4) Persistent recurrence. 128 CTAs (dir = bid/64, 8 hidden units each),
//    128 threads, all co-resident (128 <= 148 SMs at 1 CTA/SM);
//    software grid barrier per timestep.
//    Whh slice kept in smem transposed: Ws[k][j], j = gate*8 + unit_local.
// ---------------------------------------------------------------------------
#define SM_WS   (512 * 32)          // 65536 B worth of floats
#define SM_HS   (64 * 68)           // h chunk [b][k(64) pad 68]
#define SM_CS   (64 * 33)           // gate results [b][32 pad 33]
#define SM_CC   (64 * 8)            // cell state
#define SMEM_RECUR ((SM_WS + SM_HS + SM_CS + SM_CC) * 4)

__global__ void __launch_bounds__(128, 1)
k_recur(const float* __restrict__ Whf, const float* __restrict__ Whb,
        const float* __restrict__ mask, float* __restrict__ out) {
    extern __shared__ float sm[];
    float* Ws  = sm;                    // [512][32]
    float* h_s = Ws + SM_WS;            // [64][68]
    float* Cs  = h_s + SM_HS;           // [64][33]
    float* c_s = Cs + SM_CS;            // [64][8]

    const int tid = threadIdx.x;
    const int dir = blockIdx.x >> 6;
    const int u0  = (blockIdx.x & 63) * 8;
    const float* Wsrc = dir ? Whb : Whf;
    const float* X    = dir ? d_Xb : d_Xf;

    // One-time: load Whh slice transposed into Ws[k][j]
    {
        int j  = tid & 31;                              // gate*8 + unit
        int ks = (tid >> 5) * 128;                      // 4 k-slices of 128
        int grow = (j >> 3) * HID + u0 + (j & 7);       // Whh row
        const float* src = Wsrc + (size_t)grow * HID;
#pragma unroll 4
        for (int kk = 0; kk < 128; kk += 4) {
            float4 v = *(const float4*)(src + ks + kk);
            Ws[(ks + kk + 0) * 32 + j] = v.x;
            Ws[(ks + kk + 1) * 32 + j] = v.y;
            Ws[(ks + kk + 2) * 32 + j] = v.z;
            Ws[(ks + kk + 3) * 32 + j] = v.w;
        }
    }
    for (int i = tid; i < 64 * 8; i += 128) c_s[i] = 0.f;
    __syncthreads();

    const int tx = tid & 7, ty = tid >> 3;     // 8 x 16 threads
    const int b0 = ty * 4, c0 = tx * 4;        // 4x4 micro-tile
    const int lkq = tid & 15, lbr = tid >> 4;  // h-chunk load mapping

    for (int step = 0; step < LSEQ; step++) {
        const int tcur = dir ? (LSEQ - 1 - step) : step;
        const int cur = step & 1, nxt = cur ^ 1;
        const float* hsrc = d_h + (size_t)(cur * 2 + dir) * BATCH * HID;
        float*       hdst = d_h + (size_t)(nxt * 2 + dir) * BATCH * HID;

        float acc[4][4];
#pragma unroll
        for (int i = 0; i < 4; i++)
#pragma unroll
            for (int j = 0; j < 4; j++) acc[i][j] = 0.f;

        for (int kb = 0; kb < HID; kb += 64) {
            __syncthreads();
            // stage h chunk [64 b][64 k] -> h_s (coalesced global, same layout)
#pragma unroll
            for (int p = 0; p < 8; p++) {
                int b = p * 8 + lbr;
                float4 v = *(const float4*)(hsrc + (size_t)b * HID + kb + lkq * 4);
                *(float4*)&h_s[b * 68 + lkq * 4] = v;
            }
            __syncthreads();
#pragma unroll
            for (int k4 = 0; k4 < 64; k4 += 4) {
                float a[4][4], w[4][4];
#pragma unroll
                for (int i = 0; i < 4; i++)
                    *(float4*)a[i] = *(const float4*)&h_s[(b0 + i) * 68 + k4];
#pragma unroll
                for (int kk = 0; kk < 4; kk++)
                    *(float4*)w[kk] = *(const float4*)&Ws[(kb + k4 + kk) * 32 + c0];
#pragma unroll
                for (int i = 0; i < 4; i++)
#pragma unroll
                    for (int j = 0; j < 4; j++)
#pragma unroll
                        for (int kk = 0; kk < 4; kk++)
                            acc[i][j] += a[i][kk] * w[kk][j];
            }
        }

        // gate results -> Cs
#pragma unroll
        for (int i = 0; i < 4; i++)
#pragma unroll
            for (int j = 0; j < 4; j++)
                Cs[(b0 + i) * 33 + (c0 + j)] = acc[i][j];
        __syncthreads();

        // epilogue: 512 (b, unit) items, 4 per thread
#pragma unroll
        for (int it = tid; it < 512; it += 128) {
            int b = it >> 3, uu = it & 7;
            size_t xbase = ((size_t)(tcur * BATCH + b)) * G4 + u0 + uu;
            float gi = Cs[b * 33 + uu]        + X[xbase];
            float gf = Cs[b * 33 + 8  + uu]   + X[xbase + 512];
            float gg = Cs[b * 33 + 16 + uu]   + X[xbase + 1024];
            float go = Cs[b * 33 + 24 + uu]   + X[xbase + 1536];
            float si = 1.f / (1.f + __expf(-gi));
            float sf = 1.f / (1.f + __expf(-gf));
            float so = 1.f / (1.f + __expf(-go));
            float c  = sf * c_s[b * 8 + uu] + si * tanhf(gg);
            float h  = so * tanhf(c);
            float m  = mask[tcur * BATCH + b];
            c *= m; h *= m;
            c_s[b * 8 + uu] = c;
            hdst[(size_t)b * HID + u0 + uu] = h;
            out[((size_t)(tcur * BATCH + b)) * 1024 + dir * HID + u0 + uu] = h;
        }

        // ---- grid barrier (release h writes, acquire for next step) ----
        __threadfence();
        __syncthreads();
        if (tid == 0) {
            const unsigned int target = (unsigned)(step + 1);
            unsigned int arrived =
                atomicAdd((unsigned int*)&d_bar_count, 1u) + 1u;
            if (arrived == (unsigned)NBLK_REC * target) {
                __threadfence();                 // order before release
                atomicAdd((unsigned int*)&d_bar_gen, 1u);
            } else {
                unsigned ns = 64;
                while (d_bar_gen < target) {     // volatile read
                    __nanosleep(ns);
                    if (ns < 1024) ns <<= 1;     // backoff, cap 1us
                }
            }
        }
        __syncthreads();
        __threadfence();
    }
}

// ---------------------------------------------------------------------------
// Launch
// ---------------------------------------------------------------------------
extern "C" void kernel_launch(void* const* d_in, const int* in_sizes, int n_in,
                              void* d_out, int out_size) {
    const int*   data  = (const int*)  d_in[0];
    const float* mask  = (const float*)d_in[1];
    const float* table = (const float*)d_in[2];
    const float* Wih_f = (const float*)d_in[3];
    const float* Whh_f = (const float*)d_in[4];
    const float* bih_f = (const float*)d_in[5];
    const float* bhh_f = (const float*)d_in[6];
    const float* Wih_b = (const float*)d_in[7];
    const float* Whh_b = (const float*)d_in[8];
    const float* bih_b = (const float*)d_in[9];
    const float* bhh_b = (const float*)d_in[10];
    float* out = (float*)d_out;

    (void)in_sizes; (void)n_in; (void)out_size;

    // 93.4 KB dynamic smem for the recurrence kernel (idempotent; also runs
    // on the pre-capture correctness call so capture itself sees it set)
    cudaFuncSetAttribute(k_recur, cudaFuncAttributeMaxDynamicSharedMemorySize,
                         SMEM_RECUR);

    k_embed<<<(MROWS * (EMB / 4) + 255) / 256, 256>>>(data, table);

    dim3 ggrid(NCOLS / 128, MROWS / 128);   // 32 x 64
    k_gemm<<<ggrid, 256>>>(Wih_f, Wih_b, bih_f, bhh_f, bih_b, bhh_b);

    k_init<<<256, 256>>>();

    k_recur<<<NBLK_REC, 128, SMEM_RECUR>>>(Whh_f, Whh_b, mask, out);
}